// round 4
// baseline (speedup 1.0000x reference)
#include <cuda_runtime.h>
#include <math.h>
#include <stdint.h>

// BlurredNoise via legacy mma.sync tf32 (m16n8k8) implicit GEMM, 3xTF32 split.
// D[m=t, n=filter] = sum_k x[t0+m+k] * filt[f0+n, k], k in [klo_g, 5000)
// A = Toeplitz x (row-major m,k) from smem; B = filters (col-major k,n) staged
// per 32-tap chunk, pre-split into tf32 hi/lo.

#define KS      5000
#define IN_SEQ  9095
#define T_OUT   4096
#define NFILT   128
#define NROWS   16
#define NG      4
#define NF      32      // filters per group (GEMM N)
#define MT      512     // t per CTA (GEMM M)
#define THREADS 256
#define KB      32      // taps per staged chunk
#define BSTR    40      // smem floats per filter row (conflict-free: 8n+k)
#define SX_LEN  5536    // >= 32*157 + 512 + slack

struct KloArr { int v[NG]; };

__device__ __forceinline__ void tf32_split(float x, uint32_t& h, float& l) {
    uint32_t xi = __float_as_uint(x);
    h = (xi + 0x1000u) & 0xFFFFE000u;          // RN to tf32 (11-bit mantissa)
    l = x - __uint_as_float(h);                // exact residual
}

__device__ __forceinline__ void mma_tf32(float* d, const uint32_t* a,
                                         uint32_t b0, uint32_t b1) {
    asm volatile(
        "mma.sync.aligned.m16n8k8.row.col.f32.tf32.tf32.f32 "
        "{%0,%1,%2,%3}, {%4,%5,%6,%7}, {%8,%9}, {%0,%1,%2,%3};"
        : "+f"(d[0]), "+f"(d[1]), "+f"(d[2]), "+f"(d[3])
        : "r"(a[0]), "r"(a[1]), "r"(a[2]), "r"(a[3]), "r"(b0), "r"(b1));
}

__global__ __launch_bounds__(THREADS)
void blur_mma_kernel(const float* __restrict__ noise,
                     const float* __restrict__ filt,
                     const float* __restrict__ scale,
                     float* __restrict__ out,
                     KloArr klo_arr)
{
    __shared__ float sX[SX_LEN];
    __shared__ float sBh[NF * BSTR];
    __shared__ float sBl[NF * BSTR];
    __shared__ float ss[NF];

    const int tid  = threadIdx.x;
    const int g    = (NG - 1) - blockIdx.x;     // heavy group first
    const int tb   = blockIdx.y;                // t tile 0..7
    const int row  = blockIdx.z;                // 0..15

    const int t0   = tb * MT;
    const int f0   = g * NF;
    const int klo  = klo_arr.v[g];
    const int nch  = (KS - klo + KB - 1) / KB;

    // Stage x window (fp32) + scales
    {
        const int gbase = t0 + klo;
        const float* xrow = noise + (size_t)row * IN_SEQ;
        for (int i = tid; i < SX_LEN; i += THREADS) {
            const int gi = gbase + i;
            sX[i] = (gi < IN_SEQ) ? xrow[gi] : 0.0f;
        }
        if (tid < NF) ss[tid] = scale[f0 + tid];
    }

    const int lane = tid & 31;
    const int w    = tid >> 5;
    const int r    = lane >> 2;      // groupID
    const int cc   = lane & 3;       // threadID in group
    const int mb   = w * 64;         // warp m-base within CTA

    float acc[4][4][4];
#pragma unroll
    for (int mt = 0; mt < 4; ++mt)
#pragma unroll
        for (int nt = 0; nt < 4; ++nt)
#pragma unroll
            for (int j = 0; j < 4; ++j)
                acc[mt][nt][j] = 0.0f;

    for (int ch = 0; ch < nch; ++ch) {
        __syncthreads();
        // Stage B chunk: 32 filters x 32 taps, split hi/lo, stride-40 rows
        {
            const int f = tid >> 3;             // filter 0..31
            const int q = tid & 7;              // float4 within chunk
            const int k = klo + ch * KB + 4 * q;
            float4 v = make_float4(0.f, 0.f, 0.f, 0.f);
            if (k < KS)
                v = *reinterpret_cast<const float4*>(
                        filt + (size_t)(f0 + f) * KS + k);
            float4 hv, lv;
            uint32_t hb;
            tf32_split(v.x, hb, lv.x); hv.x = __uint_as_float(hb);
            tf32_split(v.y, hb, lv.y); hv.y = __uint_as_float(hb);
            tf32_split(v.z, hb, lv.z); hv.z = __uint_as_float(hb);
            tf32_split(v.w, hb, lv.w); hv.w = __uint_as_float(hb);
            *reinterpret_cast<float4*>(sBh + f * BSTR + 4 * q) = hv;
            *reinterpret_cast<float4*>(sBl + f * BSTR + 4 * q) = lv;
        }
        __syncthreads();

#pragma unroll
        for (int s = 0; s < 4; ++s) {           // k8 steps within chunk
            const int kloc = ch * KB + s * 8;

            // A fragments: Toeplitz reads + in-register tf32 split
            uint32_t ah[4][4];
            uint32_t al[4][4];
            const int ib0 = mb + r + cc + kloc;
#pragma unroll
            for (int mt = 0; mt < 4; ++mt) {
                const int ib = ib0 + mt * 16;
                // a0:(r,c)=+0  a1:(r+8,c)=+8  a2:(r,c+4)=+4  a3:(r+8,c+4)=+12
                const int off[4] = {0, 8, 4, 12};
#pragma unroll
                for (int j = 0; j < 4; ++j) {
                    float x = sX[ib + off[j]];
                    float l;
                    tf32_split(x, ah[mt][j], l);
                    al[mt][j] = __float_as_uint(l);
                }
            }

            // B fragments + MMAs, nt-major to bound register pressure
#pragma unroll
            for (int nt = 0; nt < 4; ++nt) {
                const int ba = (nt * 8 + r) * BSTR + s * 8 + cc;
                const uint32_t bh0 = __float_as_uint(sBh[ba]);
                const uint32_t bh1 = __float_as_uint(sBh[ba + 4]);
                const uint32_t bl0 = __float_as_uint(sBl[ba]);
                const uint32_t bl1 = __float_as_uint(sBl[ba + 4]);
#pragma unroll
                for (int mt = 0; mt < 4; ++mt) {
                    mma_tf32(acc[mt][nt], ah[mt], bh0, bh1);   // hi*hi
                    mma_tf32(acc[mt][nt], ah[mt], bl0, bl1);   // hi*lo
                    mma_tf32(acc[mt][nt], al[mt], bh0, bh1);   // lo*hi
                }
            }
        }
    }

    // Epilogue: scale + scattered stores
    // d frag: c0:(r, 2c) c1:(r, 2c+1) c2:(r+8, 2c) c3:(r+8, 2c+1)
#pragma unroll
    for (int nt = 0; nt < 4; ++nt) {
        const int fA = nt * 8 + 2 * cc;
        const float s0 = ss[fA];
        const float s1 = ss[fA + 1];
        float* o0 = out + ((size_t)row * NFILT + f0 + fA) * T_OUT + t0;
        float* o1 = o0 + T_OUT;
#pragma unroll
        for (int mt = 0; mt < 4; ++mt) {
            const int t = mb + mt * 16 + r;
            o0[t]     = acc[mt][nt][0] * s0;
            o1[t]     = acc[mt][nt][1] * s1;
            o0[t + 8] = acc[mt][nt][2] * s0;
            o1[t + 8] = acc[mt][nt][3] * s1;
        }
    }
}

extern "C" void kernel_launch(void* const* d_in, const int* in_sizes, int n_in,
                              void* d_out, int out_size)
{
    const float* noise = (const float*)d_in[0];   // (2,8,9095)
    const float* filt  = (const float*)d_in[1];   // (128,5000)
    const float* scale = (const float*)d_in[2];   // (1,128,1)
    float* out = (float*)d_out;                   // (2,1024,4096)

    KloArr ka;
    const double l0 = log2(250.0), l1 = log2(10000.0);
    for (int g = 0; g < NG; ++g) {
        const int i = NF * g + (NF - 1);           // longest filter in group
        double sr = exp2(l0 + (l1 - l0) * (double)i / 127.0);
        if (sr < 250.0)   sr = 250.0;
        if (sr > 10000.0) sr = 10000.0;
        const int taps = (int)ceil(sr * 0.5);
        int klo = KS - taps - 8;
        if (klo < 0) klo = 0;
        klo &= ~(KB - 1);
        ka.v[g] = klo;
    }

    dim3 grid(NG, T_OUT / MT, NROWS);             // (4, 8, 16) = 512 CTAs
    blur_mma_kernel<<<grid, THREADS>>>(noise, filt, scale, out, ka);
}